// round 9
// baseline (speedup 1.0000x reference)
#include <cuda_runtime.h>
#include <cuda_bf16.h>
#include <cuda_fp16.h>
#include <mma.h>
#include <cstdint>

using namespace nvcuda;

#define FDIM 128
#define SNEI 10
#define KCLU 16
#define NMAX 200704
#define BMAX 20480

typedef unsigned long long ull;

// scratch (__device__ globals per allocation rules)
__device__ float         g_pdot[NMAX];
__device__ float         g_c2[16];
__device__ __half        g_prod[(size_t)NMAX * FDIM];
__device__ __nv_bfloat16 g_comb_hi[(size_t)BMAX * 256];
__device__ __nv_bfloat16 g_comb_lo[(size_t)BMAX * 256];
__device__ __nv_bfloat16 g_w_hi[128 * 256];
__device__ __nv_bfloat16 g_w_lo[128 * 256];

#define FFMA2(d, a, b, c) \
    asm("fma.rn.f32x2 %0, %1, %2, %3;" : "=l"(d) : "l"(a), "l"(b), "l"(c))
#define PACK2(d, lo, hi) \
    asm("mov.b64 %0, {%1, %2};" : "=l"(d) : "f"(lo), "f"(hi))
#define UNPACK2(lo, hi, v) \
    asm("mov.b64 {%0, %1}, %2;" : "=f"(lo), "=f"(hi) : "l"(v))

// ---------------------------------------------------------------------------
// c2[k] = |center_k|^2
// ---------------------------------------------------------------------------
__global__ void c2_kernel(const float* __restrict__ center, float* __restrict__ c2)
{
    int w = threadIdx.x >> 5, l = threadIdx.x & 31;
    float4 v = ((const float4*)center)[w * 32 + l];
    float s = v.x * v.x + v.y * v.y + v.z * v.z + v.w * v.w;
#pragma unroll
    for (int o = 16; o; o >>= 1) s += __shfl_xor_sync(0xffffffffu, s, o);
    if (l == 0) c2[w] = s;
}

// ---------------------------------------------------------------------------
// weight split fp32 -> bf16 hi/lo
// ---------------------------------------------------------------------------
__global__ void wsplit_kernel(const float* __restrict__ w,
                              __nv_bfloat16* __restrict__ wh,
                              __nv_bfloat16* __restrict__ wl)
{
    int i = blockIdx.x * 256 + threadIdx.x;
    if (i < 128 * 256) {
        float v = w[i];
        __nv_bfloat16 h = __float2bfloat16(v);
        wh[i] = h;
        wl[i] = __float2bfloat16(v - __bfloat162float(h));
    }
}

// ---------------------------------------------------------------------------
// Precompute per node n (64 nodes / block, 128 threads):
//   cross via wmma (hi/lo), q scalar, coef via wmma (hi/lo), prod fp16 out.
// ---------------------------------------------------------------------------
#define RS4   132   // fp32 rows stride
#define RSB   136   // bf16 tile stride (mult of 8)
#define CSTR  20    // cross fp32 stride (mult of 4)
#define QSTR  24    // q bf16 stride (mult of 8)
#define CFSTR 132   // coef fp32 stride (mult of 4)

// dynamic smem byte offsets
#define OFF_ROWSF  0                                   // 64*132*4 = 33792
#define OFF_ROWSH  33792                               // 64*136*2 = 17408
#define OFF_ROWSL  (OFF_ROWSH + 17408)                 // 17408 (ends 68608)
#define OFF_COEF   OFF_ROWSH                           // aliases rows_h+rows_l (33792 <= 34816)
#define OFF_CENH   68608                               // 16*136*2 = 4352
#define OFF_CENL   (OFF_CENH + 4352)
#define OFF_MSKH   (OFF_CENL + 4352)
#define OFF_MSKL   (OFF_MSKH + 4352)
#define OFF_CROSS  (OFF_MSKL + 4352)                   // 64*20*4 = 5120
#define OFF_QH     (OFF_CROSS + 5120)                  // 64*24*2 = 3072
#define OFF_QL     (OFF_QH + 3072)
#define OFF_ALP    (OFF_QL + 3072)                     // 512
#define OFF_C2     (OFF_ALP + 512)                     // 64
#define OFF_PART   (OFF_C2 + 64)                       // 64*4*4 = 1024
#define PSM_BYTES  (OFF_PART + 1024)                   // ~99 KB

__global__ __launch_bounds__(128)
void precompute_kernel(const float* __restrict__ neigh_table,
                       const float* __restrict__ center,
                       const float* __restrict__ alpha,
                       const float* __restrict__ cmask,
                       const float* __restrict__ c2g,
                       __half* __restrict__ prod,
                       float* __restrict__ pdot,
                       int N)
{
    extern __shared__ __align__(16) char sm[];
    float*         rows_f = (float*)(sm + OFF_ROWSF);
    __nv_bfloat16* rows_h = (__nv_bfloat16*)(sm + OFF_ROWSH);
    __nv_bfloat16* rows_l = (__nv_bfloat16*)(sm + OFF_ROWSL);
    float*         coef_s = (float*)(sm + OFF_COEF);
    __nv_bfloat16* cen_h  = (__nv_bfloat16*)(sm + OFF_CENH);
    __nv_bfloat16* cen_l  = (__nv_bfloat16*)(sm + OFF_CENL);
    __nv_bfloat16* msk_h  = (__nv_bfloat16*)(sm + OFF_MSKH);
    __nv_bfloat16* msk_l  = (__nv_bfloat16*)(sm + OFF_MSKL);
    float*         cross  = (float*)(sm + OFF_CROSS);
    __nv_bfloat16* qh_s   = (__nv_bfloat16*)(sm + OFF_QH);
    __nv_bfloat16* ql_s   = (__nv_bfloat16*)(sm + OFF_QL);
    float*         alp_s  = (float*)(sm + OFF_ALP);
    float*         c2_s   = (float*)(sm + OFF_C2);
    float*         part_s = (float*)(sm + OFF_PART);

    int t = threadIdx.x;
    int w = t >> 5;
    int base = blockIdx.x * 64;
    int n = t & 63, h = t >> 6;

    // ---- phase 1: stage rows (fp32 + bf16 hi/lo), center, mask, alpha, c2
#pragma unroll
    for (int j = 0; j < 16; j++) {
        int i = j * 128 + t;
        int r = i >> 5, c = i & 31;
        float4 v = make_float4(0.f, 0.f, 0.f, 0.f);
        if (base + r < N)
            v = ((const float4*)neigh_table)[(size_t)(base + r) * 32 + c];
        *(float4*)&rows_f[r * RS4 + c * 4] = v;
        float vv[4] = {v.x, v.y, v.z, v.w};
        __nv_bfloat16 hh[4], ll[4];
#pragma unroll
        for (int e = 0; e < 4; e++) {
            hh[e] = __float2bfloat16(vv[e]);
            ll[e] = __float2bfloat16(vv[e] - __bfloat162float(hh[e]));
        }
        *(__nv_bfloat162*)&rows_h[r * RSB + c * 4]     = __halves2bfloat162(hh[0], hh[1]);
        *(__nv_bfloat162*)&rows_h[r * RSB + c * 4 + 2] = __halves2bfloat162(hh[2], hh[3]);
        *(__nv_bfloat162*)&rows_l[r * RSB + c * 4]     = __halves2bfloat162(ll[0], ll[1]);
        *(__nv_bfloat162*)&rows_l[r * RSB + c * 4 + 2] = __halves2bfloat162(ll[2], ll[3]);
    }
#pragma unroll
    for (int j = 0; j < 4; j++) {
        int i = j * 128 + t;          // 512 float4 over 16x128
        int r = i >> 5, c = i & 31;
        float4 cv = ((const float4*)center)[r * 32 + c];
        float4 mv = ((const float4*)cmask)[r * 32 + c];
        float cf[4] = {cv.x, cv.y, cv.z, cv.w};
        float mf[4] = {mv.x, mv.y, mv.z, mv.w};
        __nv_bfloat16 chh[4], cll[4], mhh[4], mll[4];
#pragma unroll
        for (int e = 0; e < 4; e++) {
            chh[e] = __float2bfloat16(cf[e]);
            cll[e] = __float2bfloat16(cf[e] - __bfloat162float(chh[e]));
            mhh[e] = __float2bfloat16(mf[e]);
            mll[e] = __float2bfloat16(mf[e] - __bfloat162float(mhh[e]));
        }
        *(__nv_bfloat162*)&cen_h[r * RSB + c * 4]     = __halves2bfloat162(chh[0], chh[1]);
        *(__nv_bfloat162*)&cen_h[r * RSB + c * 4 + 2] = __halves2bfloat162(chh[2], chh[3]);
        *(__nv_bfloat162*)&cen_l[r * RSB + c * 4]     = __halves2bfloat162(cll[0], cll[1]);
        *(__nv_bfloat162*)&cen_l[r * RSB + c * 4 + 2] = __halves2bfloat162(cll[2], cll[3]);
        *(__nv_bfloat162*)&msk_h[r * RSB + c * 4]     = __halves2bfloat162(mhh[0], mhh[1]);
        *(__nv_bfloat162*)&msk_h[r * RSB + c * 4 + 2] = __halves2bfloat162(mhh[2], mhh[3]);
        *(__nv_bfloat162*)&msk_l[r * RSB + c * 4]     = __halves2bfloat162(mll[0], mll[1]);
        *(__nv_bfloat162*)&msk_l[r * RSB + c * 4 + 2] = __halves2bfloat162(mll[2], mll[3]);
    }
    if (t < 32) ((float4*)alp_s)[t] = ((const float4*)alpha)[32 + t];
    if (t < 16) c2_s[t] = c2g[t];
    __syncthreads();

    // ---- phase 2a: cross[64,16] = rows @ cen^T via wmma (hi/lo)
    {
        int m0 = w * 16;
        wmma::fragment<wmma::accumulator, 16, 16, 16, float> acc;
        wmma::fill_fragment(acc, 0.0f);
#pragma unroll
        for (int kk = 0; kk < 8; kk++) {
            wmma::fragment<wmma::matrix_a, 16, 16, 16, __nv_bfloat16, wmma::row_major> ah, al;
            wmma::fragment<wmma::matrix_b, 16, 16, 16, __nv_bfloat16, wmma::col_major> bh, bl;
            wmma::load_matrix_sync(ah, &rows_h[m0 * RSB + kk * 16], RSB);
            wmma::load_matrix_sync(al, &rows_l[m0 * RSB + kk * 16], RSB);
            wmma::load_matrix_sync(bh, &cen_h[kk * 16], RSB);
            wmma::load_matrix_sync(bl, &cen_l[kk * 16], RSB);
            wmma::mma_sync(acc, ah, bh, acc);
            wmma::mma_sync(acc, al, bh, acc);
            wmma::mma_sync(acc, ah, bl, acc);
        }
        wmma::store_matrix_sync(&cross[m0 * CSTR], acc, CSTR, wmma::mem_row_major);
    }

    // ---- phase 2b: n2 & pdot halves (scalar f32x2 on fp32 rows)
    {
        ull n2p = 0ull, adp = 0ull;
        const float4* row = (const float4*)&rows_f[n * RS4 + h * 64];
#pragma unroll
        for (int q = 0; q < 16; q++) {
            float4 x = row[q];
            ull xp0, xp1;
            PACK2(xp0, x.x, x.y);
            PACK2(xp1, x.z, x.w);
            ulonglong2 ap = ((const ulonglong2*)(alp_s + h * 64))[q];
            FFMA2(n2p, xp0, xp0, n2p);
            FFMA2(n2p, xp1, xp1, n2p);
            FFMA2(adp, xp0, ap.x, adp);
            FFMA2(adp, xp1, ap.y, adp);
        }
        float lo, hi, n2v, adv;
        UNPACK2(lo, hi, n2p); n2v = lo + hi;
        UNPACK2(lo, hi, adp); adv = lo + hi;
        part_s[n * 4 + h * 2]     = n2v;
        part_s[n * 4 + h * 2 + 1] = adv;
    }
    __syncthreads();

    // ---- phase 3: q = 1/(n2 - 2 cross + c2 + 1), split bf16 hi/lo
    {
        float n2t = part_s[n * 4] + part_s[n * 4 + 2];
        float adt = part_s[n * 4 + 1] + part_s[n * 4 + 3];
        float bse = n2t + 1.0f;
#pragma unroll
        for (int j = 0; j < 8; j++) {
            int k = h * 8 + j;
            float den = fmaf(-2.0f, cross[n * CSTR + k], bse + c2_s[k]);
            float qv = 1.0f / den;
            __nv_bfloat16 qhb = __float2bfloat16(qv);
            qh_s[n * QSTR + k] = qhb;
            ql_s[n * QSTR + k] = __float2bfloat16(qv - __bfloat162float(qhb));
        }
        if (h == 0 && base + n < N) pdot[base + n] = adt;
    }
    __syncthreads();

    // ---- phase 4: coef[64,128] = q @ mask via wmma (hi/lo); aliases rows_h/l
    {
        int m0 = w * 16;
#pragma unroll
        for (int jn = 0; jn < 8; jn++) {
            wmma::fragment<wmma::accumulator, 16, 16, 16, float> acc;
            wmma::fill_fragment(acc, 0.0f);
            wmma::fragment<wmma::matrix_a, 16, 16, 16, __nv_bfloat16, wmma::row_major> aqh, aql;
            wmma::fragment<wmma::matrix_b, 16, 16, 16, __nv_bfloat16, wmma::row_major> bmh, bml;
            wmma::load_matrix_sync(aqh, &qh_s[m0 * QSTR], QSTR);
            wmma::load_matrix_sync(aql, &ql_s[m0 * QSTR], QSTR);
            wmma::load_matrix_sync(bmh, &msk_h[jn * 16], RSB);
            wmma::load_matrix_sync(bml, &msk_l[jn * 16], RSB);
            wmma::mma_sync(acc, aqh, bmh, acc);
            wmma::mma_sync(acc, aql, bmh, acc);
            wmma::mma_sync(acc, aqh, bml, acc);
            wmma::store_matrix_sync(&coef_s[m0 * CFSTR + jn * 16], acc, CFSTR,
                                    wmma::mem_row_major);
        }
    }
    __syncthreads();

    // ---- phase 5: prod[n,f] = rows[n,f] * coef[n,f] -> fp16 (half2 stores)
    {
        int fh = (t & 63) * 2;
        int nstart = h * 32;
#pragma unroll 4
        for (int nn = nstart; nn < nstart + 32; nn++) {
            if (base + nn >= N) break;
            float2 x = *(const float2*)&rows_f[nn * RS4 + fh];
            float2 c = *(const float2*)&coef_s[nn * CFSTR + fh];
            __half2 o = __floats2half2_rn(x.x * c.x, x.y * c.y);
            *(__half2*)&prod[(size_t)(base + nn) * FDIM + fh] = o;
        }
    }
}

// ---------------------------------------------------------------------------
// Row kernel: warp per row; gathers fp16 prod rows; emits bf16 hi/lo comb.
// ---------------------------------------------------------------------------
__global__ __launch_bounds__(256)
void row_kernel(const int* __restrict__ nodes,
                const int* __restrict__ neigh_idx,
                const float* __restrict__ self_table,
                const float* __restrict__ alpha,
                const float* __restrict__ pdot,
                const __half* __restrict__ prod,
                __nv_bfloat16* __restrict__ comb_hi,
                __nv_bfloat16* __restrict__ comb_lo,
                int B)
{
    int wid = threadIdx.x >> 5, lane = threadIdx.x & 31;
    int b = blockIdx.x * 8 + wid;
    if (b >= B) return;

    int node = nodes[b];
    int idx[SNEI];
#pragma unroll
    for (int s = 0; s < SNEI; s++) idx[s] = neigh_idx[b * SNEI + s];

    float4 sf = ((const float4*)self_table)[(size_t)node * 32 + lane];
    uint2 praw[SNEI];
#pragma unroll
    for (int s = 0; s < SNEI; s++)
        praw[s] = ((const uint2*)(prod + (size_t)idx[s] * FDIM))[lane];
    float pd[SNEI];
#pragma unroll
    for (int s = 0; s < SNEI; s++) pd[s] = pdot[idx[s]];

    float4 al = ((const float4*)alpha)[lane];
    float d = sf.x * al.x + sf.y * al.y + sf.z * al.z + sf.w * al.w;
#pragma unroll
    for (int o = 16; o; o >>= 1) d += __shfl_xor_sync(0xffffffffu, d, o);

    float e[SNEI], sum = 0.f;
#pragma unroll
    for (int s = 0; s < SNEI; s++) {
        float l = fmaxf(d + pd[s], 0.f);
        e[s] = __expf(l);
        sum += e[s];
    }
    float inv = 1.0f / sum;

    float4 agg = make_float4(0.f, 0.f, 0.f, 0.f);
#pragma unroll
    for (int s = 0; s < SNEI; s++) {
        float w = e[s] * inv;
        float2 f01 = __half22float2(*(const __half2*)&praw[s].x);
        float2 f23 = __half22float2(*(const __half2*)&praw[s].y);
        agg.x = fmaf(w, f01.x, agg.x);
        agg.y = fmaf(w, f01.y, agg.y);
        agg.z = fmaf(w, f23.x, agg.z);
        agg.w = fmaf(w, f23.y, agg.w);
    }

    float v[8] = {sf.x, sf.y, sf.z, sf.w, agg.x, agg.y, agg.z, agg.w};
    __nv_bfloat16 hh[8], ll[8];
#pragma unroll
    for (int i = 0; i < 8; i++) {
        hh[i] = __float2bfloat16(v[i]);
        ll[i] = __float2bfloat16(v[i] - __bfloat162float(hh[i]));
    }
    __nv_bfloat162* ch = (__nv_bfloat162*)(comb_hi + (size_t)b * 256);
    __nv_bfloat162* cl = (__nv_bfloat162*)(comb_lo + (size_t)b * 256);
    ch[lane * 2]          = __halves2bfloat162(hh[0], hh[1]);
    ch[lane * 2 + 1]      = __halves2bfloat162(hh[2], hh[3]);
    ch[64 + lane * 2]     = __halves2bfloat162(hh[4], hh[5]);
    ch[64 + lane * 2 + 1] = __halves2bfloat162(hh[6], hh[7]);
    cl[lane * 2]          = __halves2bfloat162(ll[0], ll[1]);
    cl[lane * 2 + 1]      = __halves2bfloat162(ll[2], ll[3]);
    cl[64 + lane * 2]     = __halves2bfloat162(ll[4], ll[5]);
    cl[64 + lane * 2 + 1] = __halves2bfloat162(ll[6], ll[7]);
}

// ---------------------------------------------------------------------------
// wmma bf16 GEMM, W-resident + A double-buffered (round-8 proven):
//   out = relu(Ah@Wh^T + Al@Wh^T + Ah@Wl^T)
// ---------------------------------------------------------------------------
#define WQSTR 264
#define AQSTR 40
#define W_ELEMS (128 * WQSTR)
#define ACH_ELEMS (128 * AQSTR)
#define ABUF_ELEMS (2 * ACH_ELEMS)
#define GSM_BYTES ((2 * W_ELEMS + 2 * ABUF_ELEMS) * 2)

__global__ __launch_bounds__(256, 1)
void gemm_wmma_kernel(const __nv_bfloat16* __restrict__ Ah,
                      const __nv_bfloat16* __restrict__ Al,
                      const __nv_bfloat16* __restrict__ Wh,
                      const __nv_bfloat16* __restrict__ Wl,
                      float* __restrict__ out,
                      int Brows)
{
    extern __shared__ __align__(16) __nv_bfloat16 smg[];
    __nv_bfloat16* Whs = smg;
    __nv_bfloat16* Wls = smg + W_ELEMS;
    __nv_bfloat16* Abf = smg + 2 * W_ELEMS;

    int tid = threadIdx.x;
    int w = tid >> 5;
    int wm = w & 1, wn = w >> 1;
    int row0 = blockIdx.x * 128;
    int m0 = wm * 64, n0 = wn * 32;

#pragma unroll
    for (int j = 0; j < 16; j++) {
        int i = j * 256 + tid;
        int r = i >> 5, c8 = (i & 31) * 8;
        *(uint4*)&Whs[r * WQSTR + c8] = *(const uint4*)&Wh[r * 256 + c8];
        *(uint4*)&Wls[r * WQSTR + c8] = *(const uint4*)&Wl[r * 256 + c8];
    }
#pragma unroll
    for (int j = 0; j < 2; j++) {
        int i = j * 256 + tid;
        int r = i >> 2, c8 = (i & 3) * 8;
        uint4 vh = make_uint4(0, 0, 0, 0), vl = make_uint4(0, 0, 0, 0);
        if (row0 + r < Brows) {
            vh = *(const uint4*)&Ah[(size_t)(row0 + r) * 256 + c8];
            vl = *(const uint4*)&Al[(size_t)(row0 + r) * 256 + c8];
        }
        *(uint4*)&Abf[r * AQSTR + c8]              = vh;
        *(uint4*)&Abf[ACH_ELEMS + r * AQSTR + c8]  = vl;
    }
    __syncthreads();

    wmma::fragment<wmma::accumulator, 16, 16, 16, float> acc[4][2];
#pragma unroll
    for (int i = 0; i < 4; i++)
#pragma unroll
        for (int j = 0; j < 2; j++)
            wmma::fill_fragment(acc[i][j], 0.0f);

    int buf = 0;
    uint4 ph[2], pl[2];
#pragma unroll
    for (int chunk = 0; chunk < 8; chunk++) {
        if (chunk < 7) {
            int kc = (chunk + 1) * 32;
#pragma unroll
            for (int j = 0; j < 2; j++) {
                int i = j * 256 + tid;
                int r = i >> 2, c8 = (i & 3) * 8;
                ph[j] = make_uint4(0, 0, 0, 0);
                pl[j] = make_uint4(0, 0, 0, 0);
                if (row0 + r < Brows) {
                    ph[j] = *(const uint4*)&Ah[(size_t)(row0 + r) * 256 + kc + c8];
                    pl[j] = *(const uint4*)&Al[(size_t)(row0 + r) * 256 + kc + c8];
                }
            }
        }

        const __nv_bfloat16* Ab = Abf + buf * ABUF_ELEMS;
#pragma unroll
        for (int kk = 0; kk < 32; kk += 16) {
            wmma::fragment<wmma::matrix_a, 16, 16, 16, __nv_bfloat16, wmma::row_major> ah[4], alf[4];
            wmma::fragment<wmma::matrix_b, 16, 16, 16, __nv_bfloat16, wmma::col_major> bh[2], bl[2];
#pragma unroll
            for (int i = 0; i < 4; i++) {
                wmma::load_matrix_sync(ah[i],  &Ab[(m0 + i * 16) * AQSTR + kk], AQSTR);
                wmma::load_matrix_sync(alf[i], &Ab[ACH_ELEMS + (m0 + i * 16) * AQSTR + kk], AQSTR);
            }
#pragma unroll
            for (int j = 0; j < 2; j++) {
                wmma::load_matrix_sync(bh[j], &Whs[(n0 + j * 16) * WQSTR + chunk * 32 + kk], WQSTR);
                wmma::load_matrix_sync(bl[j], &Wls[(n0 + j * 16) * WQSTR + chunk * 32 + kk], WQSTR);
            }
#pragma unroll
            for (int i = 0; i < 4; i++)
#pragma unroll
                for (int j = 0; j < 2; j++) {
                    wmma::mma_sync(acc[i][j], ah[i],  bh[j], acc[i][j]);
                    wmma::mma_sync(acc[i][j], alf[i], bh[j], acc[i][j]);
                    wmma::mma_sync(acc[i][j], ah[i],  bl[j], acc[i][j]);
                }
        }

        if (chunk < 7) {
            int nb = buf ^ 1;
#pragma unroll
            for (int j = 0; j < 2; j++) {
                int i = j * 256 + tid;
                int r = i >> 2, c8 = (i & 3) * 8;
                *(uint4*)&Abf[nb * ABUF_ELEMS + r * AQSTR + c8]             = ph[j];
                *(uint4*)&Abf[nb * ABUF_ELEMS + ACH_ELEMS + r * AQSTR + c8] = pl[j];
            }
            __syncthreads();
            buf = nb;
        }
    }

#pragma unroll
    for (int i = 0; i < 4; i++) {
        int gr = row0 + m0 + i * 16;
        if (gr < Brows) {
#pragma unroll
            for (int j = 0; j < 2; j++) {
#pragma unroll
                for (int e = 0; e < acc[i][j].num_elements; e++)
                    acc[i][j].x[e] = fmaxf(acc[i][j].x[e], 0.0f);
                wmma::store_matrix_sync(&out[(size_t)gr * FDIM + n0 + j * 16],
                                        acc[i][j], FDIM, wmma::mem_row_major);
            }
        }
    }
}

// ---------------------------------------------------------------------------
extern "C" void kernel_launch(void* const* d_in, const int* in_sizes, int n_in,
                              void* d_out, int out_size)
{
    const int*   nodes      = (const int*)d_in[0];
    const int*   neigh_idx  = (const int*)d_in[1];
    const float* self_table = (const float*)d_in[2];
    const float* neigh_tab  = (const float*)d_in[3];
    const float* center     = (const float*)d_in[4];
    const float* cmask      = (const float*)d_in[5];
    const float* weight     = (const float*)d_in[6];
    const float* alpha      = (const float*)d_in[7];
    float*       out        = (float*)d_out;

    int B = in_sizes[0];
    int N = in_sizes[3] / FDIM;

    float *pd, *c2;
    __half* prod;
    __nv_bfloat16 *ch, *cl, *wh, *wl;
    cudaGetSymbolAddress((void**)&prod, g_prod);
    cudaGetSymbolAddress((void**)&pd,   g_pdot);
    cudaGetSymbolAddress((void**)&c2,   g_c2);
    cudaGetSymbolAddress((void**)&ch,   g_comb_hi);
    cudaGetSymbolAddress((void**)&cl,   g_comb_lo);
    cudaGetSymbolAddress((void**)&wh,   g_w_hi);
    cudaGetSymbolAddress((void**)&wl,   g_w_lo);

    cudaFuncSetAttribute(precompute_kernel,
                         cudaFuncAttributeMaxDynamicSharedMemorySize, PSM_BYTES);
    cudaFuncSetAttribute(gemm_wmma_kernel,
                         cudaFuncAttributeMaxDynamicSharedMemorySize, GSM_BYTES);

    c2_kernel<<<1, 512>>>(center, c2);
    wsplit_kernel<<<128, 256>>>(weight, wh, wl);
    precompute_kernel<<<(N + 63) / 64, 128, PSM_BYTES>>>(neigh_tab, center, alpha,
                                                         cmask, c2, prod, pd, N);
    row_kernel<<<(B + 7) / 8, 256>>>(nodes, neigh_idx, self_table, alpha,
                                     pd, prod, ch, cl, B);
    gemm_wmma_kernel<<<(B + 127) / 128, 256, GSM_BYTES>>>(ch, cl, wh, wl, out, B);
}

// round 10
// speedup vs baseline: 1.3465x; 1.3465x over previous
#include <cuda_runtime.h>
#include <cuda_bf16.h>
#include <cuda_fp16.h>
#include <mma.h>
#include <cstdint>

using namespace nvcuda;

#define FDIM 128
#define SNEI 10
#define KCLU 16
#define NMAX 200704
#define BMAX 20480

typedef unsigned long long ull;

// scratch (__device__ globals per allocation rules)
__device__ float         g_pdot[NMAX];
__device__ float         g_c2[16];
__device__ __half        g_prod[(size_t)NMAX * FDIM];
__device__ __nv_bfloat16 g_comb_hi[(size_t)BMAX * 256];
__device__ __nv_bfloat16 g_comb_lo[(size_t)BMAX * 256];
__device__ __nv_bfloat16 g_w_hi[128 * 256];
__device__ __nv_bfloat16 g_w_lo[128 * 256];

#define FFMA2(d, a, b, c) \
    asm("fma.rn.f32x2 %0, %1, %2, %3;" : "=l"(d) : "l"(a), "l"(b), "l"(c))
#define PACK2(d, lo, hi) \
    asm("mov.b64 %0, {%1, %2};" : "=l"(d) : "f"(lo), "f"(hi))
#define UNPACK2(lo, hi, v) \
    asm("mov.b64 {%0, %1}, %2;" : "=f"(lo), "=f"(hi) : "l"(v))

// ---------------------------------------------------------------------------
// prep: blocks 0..63 split W into bf16 hi/lo (512 thr); block 64 computes c2.
// ---------------------------------------------------------------------------
__global__ __launch_bounds__(512)
void prep_kernel(const float* __restrict__ w,
                 __nv_bfloat16* __restrict__ wh,
                 __nv_bfloat16* __restrict__ wl,
                 const float* __restrict__ center,
                 float* __restrict__ c2)
{
    if (blockIdx.x < 64) {
        int i = blockIdx.x * 512 + threadIdx.x;
        float v = w[i];
        __nv_bfloat16 h = __float2bfloat16(v);
        wh[i] = h;
        wl[i] = __float2bfloat16(v - __bfloat162float(h));
    } else {
        int wp = threadIdx.x >> 5, l = threadIdx.x & 31;  // 16 warps
        float4 v = ((const float4*)center)[wp * 32 + l];
        float s = v.x * v.x + v.y * v.y + v.z * v.z + v.w * v.w;
#pragma unroll
        for (int o = 16; o; o >>= 1) s += __shfl_xor_sync(0xffffffffu, s, o);
        if (l == 0) c2[wp] = s;
    }
}

// ---------------------------------------------------------------------------
// Precompute per node n (32 nodes / block, 128 threads, quarter-row split):
//   pdot[n]   = row . a_neigh
//   q[n][k]   = 1/(n2 - 2 cross[k] + 1 + c2[k])
//   prod[n,f] = row[f] * sum_k q[n][k]*mask[k][f]   (fp16 out)
// ---------------------------------------------------------------------------
#define RS4  132
#define QST  20     // q row stride in floats (80 B, 16B-aligned rows)

__global__ __launch_bounds__(128)
void precompute_kernel(const float* __restrict__ neigh_table,
                       const float* __restrict__ center,
                       const float* __restrict__ alpha,
                       const float* __restrict__ cmask,
                       const float* __restrict__ c2g,
                       __half* __restrict__ prod,
                       float* __restrict__ pdot,
                       int N)
{
    __shared__ __align__(16) float rows_s[32 * RS4];     // 16896 B
    __shared__ __align__(16) float cen_s[16 * 128];      // 8192 B (reused as partials)
    __shared__ __align__(16) float alp_s[128];
    __shared__ __align__(16) float q_s[32 * QST];        // 2560 B
    __shared__ float c2_s[16];

    int t = threadIdx.x;
    int base = blockIdx.x * 32;
    int n = t & 31, h = t >> 5;          // h in 0..3 (quarter rows)

    // mask registers (thread = feature t)
    ull mp[8];
#pragma unroll
    for (int kp = 0; kp < 8; kp++) {
        float m0 = cmask[(2 * kp) * FDIM + t];
        float m1 = cmask[(2 * kp + 1) * FDIM + t];
        PACK2(mp[kp], m0, m1);
    }

    // ---- stage 32 rows + center + alpha_neigh + c2 ----
#pragma unroll
    for (int j = 0; j < 8; j++) {
        int i = j * 128 + t;             // float4 index over 32x128 tile
        int r = i >> 5, c = i & 31;
        float4 v = make_float4(0.f, 0.f, 0.f, 0.f);
        if (base + r < N)
            v = ((const float4*)neigh_table)[(size_t)(base + r) * 32 + c];
        *(float4*)&rows_s[r * RS4 + c * 4] = v;
    }
#pragma unroll
    for (int j = 0; j < 4; j++)
        ((float4*)cen_s)[j * 128 + t] = ((const float4*)center)[j * 128 + t];
    if (t < 32) ((float4*)alp_s)[t] = ((const float4*)alpha)[32 + t];
    if (t < 16) c2_s[t] = c2g[t];
    __syncthreads();

    // ---- phase 2: quarter-row reductions (cross x16, n2, pdot) ----
    ull crp[16], n2p = 0ull, adp = 0ull;
#pragma unroll
    for (int k = 0; k < 16; k++) crp[k] = 0ull;

    {
        const float4* row = (const float4*)&rows_s[n * RS4 + h * 32];
#pragma unroll
        for (int q = 0; q < 8; q++) {
            float4 x = row[q];
            ull xp0, xp1;
            PACK2(xp0, x.x, x.y);
            PACK2(xp1, x.z, x.w);
            ulonglong2 ap = ((const ulonglong2*)(alp_s + h * 32))[q];
            FFMA2(adp, xp0, ap.x, adp);
            FFMA2(adp, xp1, ap.y, adp);
            FFMA2(n2p, xp0, xp0, n2p);
            FFMA2(n2p, xp1, xp1, n2p);
#pragma unroll
            for (int k = 0; k < 16; k++) {
                ulonglong2 cp = ((const ulonglong2*)(cen_s + k * 128 + h * 32))[q];
                FFMA2(crp[k], xp0, cp.x, crp[k]);
                FFMA2(crp[k], xp1, cp.y, crp[k]);
            }
        }
    }

    float cr[16], n2v, adv;
    {
        float lo, hi;
#pragma unroll
        for (int k = 0; k < 16; k++) { UNPACK2(lo, hi, crp[k]); cr[k] = lo + hi; }
        UNPACK2(lo, hi, n2p); n2v = lo + hi;
        UNPACK2(lo, hi, adp); adv = lo + hi;
    }
    __syncthreads();                 // cen_s dead -> reuse as partial buffer
    float* part_s = cen_s;           // [3][32][20] floats = 7680 B <= 8192
    if (h >= 1) {
        float* p = &part_s[(h - 1) * 640 + n * 20];
#pragma unroll
        for (int k = 0; k < 16; k++) p[k] = cr[k];
        p[16] = n2v;
        p[17] = adv;
    }
    __syncthreads();
    if (h == 0) {
        float n2t = n2v, adt = adv;
#pragma unroll
        for (int p = 0; p < 3; p++) {
            n2t += part_s[p * 640 + n * 20 + 16];
            adt += part_s[p * 640 + n * 20 + 17];
        }
        float bse = n2t + 1.0f;
#pragma unroll
        for (int k = 0; k < 16; k++) {
            float crt = cr[k] + part_s[n * 20 + k] + part_s[640 + n * 20 + k]
                      + part_s[1280 + n * 20 + k];
            float den = fmaf(-2.0f, crt, bse + c2_s[k]);
            q_s[n * QST + k] = 1.0f / den;
        }
        if (base + n < N) pdot[base + n] = adt;
    }
    __syncthreads();

    // ---- phase 3: thread = feature t; loop 32 nodes; LDS.128 q loads ----
    int nlim = min(32, N - base);
    for (int nn = 0; nn < nlim; nn++) {
        const ulonglong2* qp2 = (const ulonglong2*)&q_s[nn * QST];
        ull acc = 0ull;
#pragma unroll
        for (int kp = 0; kp < 4; kp++) {
            ulonglong2 qq = qp2[kp];
            FFMA2(acc, qq.x, mp[2 * kp],     acc);
            FFMA2(acc, qq.y, mp[2 * kp + 1], acc);
        }
        float lo, hi; UNPACK2(lo, hi, acc);
        float x = rows_s[nn * RS4 + t];
        prod[(size_t)(base + nn) * FDIM + t] = __float2half(x * (lo + hi));
    }
}

// ---------------------------------------------------------------------------
// Row kernel: warp per row; gathers fp16 prod rows; emits bf16 hi/lo comb.
// (unchanged from round 8)
// ---------------------------------------------------------------------------
__global__ __launch_bounds__(256)
void row_kernel(const int* __restrict__ nodes,
                const int* __restrict__ neigh_idx,
                const float* __restrict__ self_table,
                const float* __restrict__ alpha,
                const float* __restrict__ pdot,
                const __half* __restrict__ prod,
                __nv_bfloat16* __restrict__ comb_hi,
                __nv_bfloat16* __restrict__ comb_lo,
                int B)
{
    int wid = threadIdx.x >> 5, lane = threadIdx.x & 31;
    int b = blockIdx.x * 8 + wid;
    if (b >= B) return;

    int node = nodes[b];
    int idx[SNEI];
#pragma unroll
    for (int s = 0; s < SNEI; s++) idx[s] = neigh_idx[b * SNEI + s];

    float4 sf = ((const float4*)self_table)[(size_t)node * 32 + lane];
    uint2 praw[SNEI];
#pragma unroll
    for (int s = 0; s < SNEI; s++)
        praw[s] = ((const uint2*)(prod + (size_t)idx[s] * FDIM))[lane];
    float pd[SNEI];
#pragma unroll
    for (int s = 0; s < SNEI; s++) pd[s] = pdot[idx[s]];

    float4 al = ((const float4*)alpha)[lane];
    float d = sf.x * al.x + sf.y * al.y + sf.z * al.z + sf.w * al.w;
#pragma unroll
    for (int o = 16; o; o >>= 1) d += __shfl_xor_sync(0xffffffffu, d, o);

    float e[SNEI], sum = 0.f;
#pragma unroll
    for (int s = 0; s < SNEI; s++) {
        float l = fmaxf(d + pd[s], 0.f);
        e[s] = __expf(l);
        sum += e[s];
    }
    float inv = 1.0f / sum;

    float4 agg = make_float4(0.f, 0.f, 0.f, 0.f);
#pragma unroll
    for (int s = 0; s < SNEI; s++) {
        float w = e[s] * inv;
        float2 f01 = __half22float2(*(const __half2*)&praw[s].x);
        float2 f23 = __half22float2(*(const __half2*)&praw[s].y);
        agg.x = fmaf(w, f01.x, agg.x);
        agg.y = fmaf(w, f01.y, agg.y);
        agg.z = fmaf(w, f23.x, agg.z);
        agg.w = fmaf(w, f23.y, agg.w);
    }

    float v[8] = {sf.x, sf.y, sf.z, sf.w, agg.x, agg.y, agg.z, agg.w};
    __nv_bfloat16 hh[8], ll[8];
#pragma unroll
    for (int i = 0; i < 8; i++) {
        hh[i] = __float2bfloat16(v[i]);
        ll[i] = __float2bfloat16(v[i] - __bfloat162float(hh[i]));
    }
    __nv_bfloat162* ch = (__nv_bfloat162*)(comb_hi + (size_t)b * 256);
    __nv_bfloat162* cl = (__nv_bfloat162*)(comb_lo + (size_t)b * 256);
    ch[lane * 2]          = __halves2bfloat162(hh[0], hh[1]);
    ch[lane * 2 + 1]      = __halves2bfloat162(hh[2], hh[3]);
    ch[64 + lane * 2]     = __halves2bfloat162(hh[4], hh[5]);
    ch[64 + lane * 2 + 1] = __halves2bfloat162(hh[6], hh[7]);
    cl[lane * 2]          = __halves2bfloat162(ll[0], ll[1]);
    cl[lane * 2 + 1]      = __halves2bfloat162(ll[2], ll[3]);
    cl[64 + lane * 2]     = __halves2bfloat162(ll[4], ll[5]);
    cl[64 + lane * 2 + 1] = __halves2bfloat162(ll[6], ll[7]);
}

// ---------------------------------------------------------------------------
// wmma bf16 GEMM, W-resident + A double-buffered (round-8 proven):
//   out = relu(Ah@Wh^T + Al@Wh^T + Ah@Wl^T)
// ---------------------------------------------------------------------------
#define WQSTR 264
#define AQSTR 40
#define W_ELEMS (128 * WQSTR)
#define ACH_ELEMS (128 * AQSTR)
#define ABUF_ELEMS (2 * ACH_ELEMS)
#define GSM_BYTES ((2 * W_ELEMS + 2 * ABUF_ELEMS) * 2)

__global__ __launch_bounds__(256, 1)
void gemm_wmma_kernel(const __nv_bfloat16* __restrict__ Ah,
                      const __nv_bfloat16* __restrict__ Al,
                      const __nv_bfloat16* __restrict__ Wh,
                      const __nv_bfloat16* __restrict__ Wl,
                      float* __restrict__ out,
                      int Brows)
{
    extern __shared__ __align__(16) __nv_bfloat16 smg[];
    __nv_bfloat16* Whs = smg;
    __nv_bfloat16* Wls = smg + W_ELEMS;
    __nv_bfloat16* Abf = smg + 2 * W_ELEMS;

    int tid = threadIdx.x;
    int w = tid >> 5;
    int wm = w & 1, wn = w >> 1;
    int row0 = blockIdx.x * 128;
    int m0 = wm * 64, n0 = wn * 32;

#pragma unroll
    for (int j = 0; j < 16; j++) {
        int i = j * 256 + tid;
        int r = i >> 5, c8 = (i & 31) * 8;
        *(uint4*)&Whs[r * WQSTR + c8] = *(const uint4*)&Wh[r * 256 + c8];
        *(uint4*)&Wls[r * WQSTR + c8] = *(const uint4*)&Wl[r * 256 + c8];
    }
#pragma unroll
    for (int j = 0; j < 2; j++) {
        int i = j * 256 + tid;
        int r = i >> 2, c8 = (i & 3) * 8;
        uint4 vh = make_uint4(0, 0, 0, 0), vl = make_uint4(0, 0, 0, 0);
        if (row0 + r < Brows) {
            vh = *(const uint4*)&Ah[(size_t)(row0 + r) * 256 + c8];
            vl = *(const uint4*)&Al[(size_t)(row0 + r) * 256 + c8];
        }
        *(uint4*)&Abf[r * AQSTR + c8]              = vh;
        *(uint4*)&Abf[ACH_ELEMS + r * AQSTR + c8]  = vl;
    }
    __syncthreads();

    wmma::fragment<wmma::accumulator, 16, 16, 16, float> acc[4][2];
#pragma unroll
    for (int i = 0; i < 4; i++)
#pragma unroll
        for (int j = 0; j < 2; j++)
            wmma::fill_fragment(acc[i][j], 0.0f);

    int buf = 0;
    uint4 ph[2], pl[2];
#pragma unroll
    for (int chunk = 0; chunk < 8; chunk++) {
        if (chunk < 7) {
            int kc = (chunk + 1) * 32;
#pragma unroll
            for (int j = 0; j < 2; j++) {
                int i = j * 256 + tid;
                int r = i >> 2, c8 = (i & 3) * 8;
                ph[j] = make_uint4(0, 0, 0, 0);
                pl[j] = make_uint4(0, 0, 0, 0);
                if (row0 + r < Brows) {
                    ph[j] = *(const uint4*)&Ah[(size_t)(row0 + r) * 256 + kc + c8];
                    pl[j] = *(const uint4*)&Al[(size_t)(row0 + r) * 256 + kc + c8];
                }
            }
        }

        const __nv_bfloat16* Ab = Abf + buf * ABUF_ELEMS;
#pragma unroll
        for (int kk = 0; kk < 32; kk += 16) {
            wmma::fragment<wmma::matrix_a, 16, 16, 16, __nv_bfloat16, wmma::row_major> ah[4], alf[4];
            wmma::fragment<wmma::matrix_b, 16, 16, 16, __nv_bfloat16, wmma::col_major> bh[2], bl[2];
#pragma unroll
            for (int i = 0; i < 4; i++) {
                wmma::load_matrix_sync(ah[i],  &Ab[(m0 + i * 16) * AQSTR + kk], AQSTR);
                wmma::load_matrix_sync(alf[i], &Ab[ACH_ELEMS + (m0 + i * 16) * AQSTR + kk], AQSTR);
            }
#pragma unroll
            for (int j = 0; j < 2; j++) {
                wmma::load_matrix_sync(bh[j], &Whs[(n0 + j * 16) * WQSTR + chunk * 32 + kk], WQSTR);
                wmma::load_matrix_sync(bl[j], &Wls[(n0 + j * 16) * WQSTR + chunk * 32 + kk], WQSTR);
            }
#pragma unroll
            for (int i = 0; i < 4; i++)
#pragma unroll
                for (int j = 0; j < 2; j++) {
                    wmma::mma_sync(acc[i][j], ah[i],  bh[j], acc[i][j]);
                    wmma::mma_sync(acc[i][j], alf[i], bh[j], acc[i][j]);
                    wmma::mma_sync(acc[i][j], ah[i],  bl[j], acc[i][j]);
                }
        }

        if (chunk < 7) {
            int nb = buf ^ 1;
#pragma unroll
            for (int j = 0; j < 2; j++) {
                int i = j * 256 + tid;
                int r = i >> 2, c8 = (i & 3) * 8;
                *(uint4*)&Abf[nb * ABUF_ELEMS + r * AQSTR + c8]             = ph[j];
                *(uint4*)&Abf[nb * ABUF_ELEMS + ACH_ELEMS + r * AQSTR + c8] = pl[j];
            }
            __syncthreads();
            buf = nb;
        }
    }

#pragma unroll
    for (int i = 0; i < 4; i++) {
        int gr = row0 + m0 + i * 16;
        if (gr < Brows) {
#pragma unroll
            for (int j = 0; j < 2; j++) {
#pragma unroll
                for (int e = 0; e < acc[i][j].num_elements; e++)
                    acc[i][j].x[e] = fmaxf(acc[i][j].x[e], 0.0f);
                wmma::store_matrix_sync(&out[(size_t)gr * FDIM + n0 + j * 16],
                                        acc[i][j], FDIM, wmma::mem_row_major);
            }
        }
    }
}

// ---------------------------------------------------------------------------
extern "C" void kernel_launch(void* const* d_in, const int* in_sizes, int n_in,
                              void* d_out, int out_size)
{
    const int*   nodes      = (const int*)d_in[0];
    const int*   neigh_idx  = (const int*)d_in[1];
    const float* self_table = (const float*)d_in[2];
    const float* neigh_tab  = (const float*)d_in[3];
    const float* center     = (const float*)d_in[4];
    const float* cmask      = (const float*)d_in[5];
    const float* weight     = (const float*)d_in[6];
    const float* alpha      = (const float*)d_in[7];
    float*       out        = (float*)d_out;

    int B = in_sizes[0];
    int N = in_sizes[3] / FDIM;

    float *pd, *c2;
    __half* prod;
    __nv_bfloat16 *ch, *cl, *wh, *wl;
    cudaGetSymbolAddress((void**)&prod, g_prod);
    cudaGetSymbolAddress((void**)&pd,   g_pdot);
    cudaGetSymbolAddress((void**)&c2,   g_c2);
    cudaGetSymbolAddress((void**)&ch,   g_comb_hi);
    cudaGetSymbolAddress((void**)&cl,   g_comb_lo);
    cudaGetSymbolAddress((void**)&wh,   g_w_hi);
    cudaGetSymbolAddress((void**)&wl,   g_w_lo);

    cudaFuncSetAttribute(gemm_wmma_kernel,
                         cudaFuncAttributeMaxDynamicSharedMemorySize, GSM_BYTES);

    prep_kernel<<<65, 512>>>(weight, wh, wl, center, c2);
    precompute_kernel<<<(N + 31) / 32, 128>>>(neigh_tab, center, alpha, cmask,
                                              c2, prod, pd, N);
    row_kernel<<<(B + 7) / 8, 256>>>(nodes, neigh_idx, self_table, alpha,
                                     pd, prod, ch, cl, B);
    gemm_wmma_kernel<<<(B + 127) / 128, 256, GSM_BYTES>>>(ch, cl, wh, wl, out, B);
}

// round 11
// speedup vs baseline: 1.3476x; 1.0008x over previous
#include <cuda_runtime.h>
#include <cuda_bf16.h>
#include <cuda_fp16.h>
#include <mma.h>
#include <cstdint>

using namespace nvcuda;

#define FDIM 128
#define SNEI 10
#define KCLU 16
#define NMAX 200704
#define BMAX 20480

typedef unsigned long long ull;

// scratch (__device__ globals per allocation rules)
__device__ float         g_pdot[NMAX];
__device__ float         g_c2[16];
__device__ __half        g_prod[(size_t)NMAX * FDIM];
__device__ __nv_bfloat16 g_comb_hi[(size_t)BMAX * 256];
__device__ __nv_bfloat16 g_comb_lo[(size_t)BMAX * 256];
__device__ __nv_bfloat16 g_w_hi[128 * 256];
__device__ __nv_bfloat16 g_w_lo[128 * 256];

#define FFMA2(d, a, b, c) \
    asm("fma.rn.f32x2 %0, %1, %2, %3;" : "=l"(d) : "l"(a), "l"(b), "l"(c))
#define PACK2(d, lo, hi) \
    asm("mov.b64 %0, {%1, %2};" : "=l"(d) : "f"(lo), "f"(hi))
#define UNPACK2(lo, hi, v) \
    asm("mov.b64 {%0, %1}, %2;" : "=f"(lo), "=f"(hi) : "l"(v))

// ---------------------------------------------------------------------------
// prep: blocks 0..63 split W into bf16 hi/lo (512 thr); block 64 computes c2.
// ---------------------------------------------------------------------------
__global__ __launch_bounds__(512)
void prep_kernel(const float* __restrict__ w,
                 __nv_bfloat16* __restrict__ wh,
                 __nv_bfloat16* __restrict__ wl,
                 const float* __restrict__ center,
                 float* __restrict__ c2)
{
    if (blockIdx.x < 64) {
        int i = blockIdx.x * 512 + threadIdx.x;
        float v = w[i];
        __nv_bfloat16 h = __float2bfloat16(v);
        wh[i] = h;
        wl[i] = __float2bfloat16(v - __bfloat162float(h));
    } else {
        int wp = threadIdx.x >> 5, l = threadIdx.x & 31;  // 16 warps
        float4 v = ((const float4*)center)[wp * 32 + l];
        float s = v.x * v.x + v.y * v.y + v.z * v.z + v.w * v.w;
#pragma unroll
        for (int o = 16; o; o >>= 1) s += __shfl_xor_sync(0xffffffffu, s, o);
        if (l == 0) c2[wp] = s;
    }
}

// ---------------------------------------------------------------------------
// Precompute per node n (32 nodes / block, 128 threads, quarter-row split)
// (round-10 proven version)
// ---------------------------------------------------------------------------
#define RS4  132
#define QST  20

__global__ __launch_bounds__(128)
void precompute_kernel(const float* __restrict__ neigh_table,
                       const float* __restrict__ center,
                       const float* __restrict__ alpha,
                       const float* __restrict__ cmask,
                       const float* __restrict__ c2g,
                       __half* __restrict__ prod,
                       float* __restrict__ pdot,
                       int N)
{
    __shared__ __align__(16) float rows_s[32 * RS4];
    __shared__ __align__(16) float cen_s[16 * 128];
    __shared__ __align__(16) float alp_s[128];
    __shared__ __align__(16) float q_s[32 * QST];
    __shared__ float c2_s[16];

    int t = threadIdx.x;
    int base = blockIdx.x * 32;
    int n = t & 31, h = t >> 5;

    ull mp[8];
#pragma unroll
    for (int kp = 0; kp < 8; kp++) {
        float m0 = cmask[(2 * kp) * FDIM + t];
        float m1 = cmask[(2 * kp + 1) * FDIM + t];
        PACK2(mp[kp], m0, m1);
    }

#pragma unroll
    for (int j = 0; j < 8; j++) {
        int i = j * 128 + t;
        int r = i >> 5, c = i & 31;
        float4 v = make_float4(0.f, 0.f, 0.f, 0.f);
        if (base + r < N)
            v = ((const float4*)neigh_table)[(size_t)(base + r) * 32 + c];
        *(float4*)&rows_s[r * RS4 + c * 4] = v;
    }
#pragma unroll
    for (int j = 0; j < 4; j++)
        ((float4*)cen_s)[j * 128 + t] = ((const float4*)center)[j * 128 + t];
    if (t < 32) ((float4*)alp_s)[t] = ((const float4*)alpha)[32 + t];
    if (t < 16) c2_s[t] = c2g[t];
    __syncthreads();

    ull crp[16], n2p = 0ull, adp = 0ull;
#pragma unroll
    for (int k = 0; k < 16; k++) crp[k] = 0ull;

    {
        const float4* row = (const float4*)&rows_s[n * RS4 + h * 32];
#pragma unroll
        for (int q = 0; q < 8; q++) {
            float4 x = row[q];
            ull xp0, xp1;
            PACK2(xp0, x.x, x.y);
            PACK2(xp1, x.z, x.w);
            ulonglong2 ap = ((const ulonglong2*)(alp_s + h * 32))[q];
            FFMA2(adp, xp0, ap.x, adp);
            FFMA2(adp, xp1, ap.y, adp);
            FFMA2(n2p, xp0, xp0, n2p);
            FFMA2(n2p, xp1, xp1, n2p);
#pragma unroll
            for (int k = 0; k < 16; k++) {
                ulonglong2 cp = ((const ulonglong2*)(cen_s + k * 128 + h * 32))[q];
                FFMA2(crp[k], xp0, cp.x, crp[k]);
                FFMA2(crp[k], xp1, cp.y, crp[k]);
            }
        }
    }

    float cr[16], n2v, adv;
    {
        float lo, hi;
#pragma unroll
        for (int k = 0; k < 16; k++) { UNPACK2(lo, hi, crp[k]); cr[k] = lo + hi; }
        UNPACK2(lo, hi, n2p); n2v = lo + hi;
        UNPACK2(lo, hi, adp); adv = lo + hi;
    }
    __syncthreads();
    float* part_s = cen_s;
    if (h >= 1) {
        float* p = &part_s[(h - 1) * 640 + n * 20];
#pragma unroll
        for (int k = 0; k < 16; k++) p[k] = cr[k];
        p[16] = n2v;
        p[17] = adv;
    }
    __syncthreads();
    if (h == 0) {
        float n2t = n2v, adt = adv;
#pragma unroll
        for (int p = 0; p < 3; p++) {
            n2t += part_s[p * 640 + n * 20 + 16];
            adt += part_s[p * 640 + n * 20 + 17];
        }
        float bse = n2t + 1.0f;
#pragma unroll
        for (int k = 0; k < 16; k++) {
            float crt = cr[k] + part_s[n * 20 + k] + part_s[640 + n * 20 + k]
                      + part_s[1280 + n * 20 + k];
            float den = fmaf(-2.0f, crt, bse + c2_s[k]);
            q_s[n * QST + k] = 1.0f / den;
        }
        if (base + n < N) pdot[base + n] = adt;
    }
    __syncthreads();

    int nlim = min(32, N - base);
    for (int nn = 0; nn < nlim; nn++) {
        const ulonglong2* qp2 = (const ulonglong2*)&q_s[nn * QST];
        ull acc = 0ull;
#pragma unroll
        for (int kp = 0; kp < 4; kp++) {
            ulonglong2 qq = qp2[kp];
            FFMA2(acc, qq.x, mp[2 * kp],     acc);
            FFMA2(acc, qq.y, mp[2 * kp + 1], acc);
        }
        float lo, hi; UNPACK2(lo, hi, acc);
        float x = rows_s[nn * RS4 + t];
        prod[(size_t)(base + nn) * FDIM + t] = __float2half(x * (lo + hi));
    }
}

// ---------------------------------------------------------------------------
// Row kernel: warp per row; gathers fp16 prod rows; emits bf16 hi/lo comb.
// (round-8 proven)
// ---------------------------------------------------------------------------
__global__ __launch_bounds__(256)
void row_kernel(const int* __restrict__ nodes,
                const int* __restrict__ neigh_idx,
                const float* __restrict__ self_table,
                const float* __restrict__ alpha,
                const float* __restrict__ pdot,
                const __half* __restrict__ prod,
                __nv_bfloat16* __restrict__ comb_hi,
                __nv_bfloat16* __restrict__ comb_lo,
                int B)
{
    int wid = threadIdx.x >> 5, lane = threadIdx.x & 31;
    int b = blockIdx.x * 8 + wid;
    if (b >= B) return;

    int node = nodes[b];
    int idx[SNEI];
#pragma unroll
    for (int s = 0; s < SNEI; s++) idx[s] = neigh_idx[b * SNEI + s];

    float4 sf = ((const float4*)self_table)[(size_t)node * 32 + lane];
    uint2 praw[SNEI];
#pragma unroll
    for (int s = 0; s < SNEI; s++)
        praw[s] = ((const uint2*)(prod + (size_t)idx[s] * FDIM))[lane];
    float pd[SNEI];
#pragma unroll
    for (int s = 0; s < SNEI; s++) pd[s] = pdot[idx[s]];

    float4 al = ((const float4*)alpha)[lane];
    float d = sf.x * al.x + sf.y * al.y + sf.z * al.z + sf.w * al.w;
#pragma unroll
    for (int o = 16; o; o >>= 1) d += __shfl_xor_sync(0xffffffffu, d, o);

    float e[SNEI], sum = 0.f;
#pragma unroll
    for (int s = 0; s < SNEI; s++) {
        float l = fmaxf(d + pd[s], 0.f);
        e[s] = __expf(l);
        sum += e[s];
    }
    float inv = 1.0f / sum;

    float4 agg = make_float4(0.f, 0.f, 0.f, 0.f);
#pragma unroll
    for (int s = 0; s < SNEI; s++) {
        float w = e[s] * inv;
        float2 f01 = __half22float2(*(const __half2*)&praw[s].x);
        float2 f23 = __half22float2(*(const __half2*)&praw[s].y);
        agg.x = fmaf(w, f01.x, agg.x);
        agg.y = fmaf(w, f01.y, agg.y);
        agg.z = fmaf(w, f23.x, agg.z);
        agg.w = fmaf(w, f23.y, agg.w);
    }

    float v[8] = {sf.x, sf.y, sf.z, sf.w, agg.x, agg.y, agg.z, agg.w};
    __nv_bfloat16 hh[8], ll[8];
#pragma unroll
    for (int i = 0; i < 8; i++) {
        hh[i] = __float2bfloat16(v[i]);
        ll[i] = __float2bfloat16(v[i] - __bfloat162float(hh[i]));
    }
    __nv_bfloat162* ch = (__nv_bfloat162*)(comb_hi + (size_t)b * 256);
    __nv_bfloat162* cl = (__nv_bfloat162*)(comb_lo + (size_t)b * 256);
    ch[lane * 2]          = __halves2bfloat162(hh[0], hh[1]);
    ch[lane * 2 + 1]      = __halves2bfloat162(hh[2], hh[3]);
    ch[64 + lane * 2]     = __halves2bfloat162(hh[4], hh[5]);
    ch[64 + lane * 2 + 1] = __halves2bfloat162(hh[6], hh[7]);
    cl[lane * 2]          = __halves2bfloat162(ll[0], ll[1]);
    cl[lane * 2 + 1]      = __halves2bfloat162(ll[2], ll[3]);
    cl[64 + lane * 2]     = __halves2bfloat162(ll[4], ll[5]);
    cl[64 + lane * 2 + 1] = __halves2bfloat162(ll[6], ll[7]);
}

// ---------------------------------------------------------------------------
// wmma bf16 GEMM, occupancy-first retile:
//   out = relu(Ah@Wh^T + Al@Wh^T + Ah@Wl^T)
// BM=64, BN=128, 256 threads (8 warps, 2x4 -> 32x32 warp tiles), grid=313.
// Per-chunk staging of A and W hi/lo (30.7 KB smem), register prefetch,
// single smem buffer, 2 blocks/SM.
// ---------------------------------------------------------------------------
#define GBM  64
#define GAST 40     // A smem stride (halves)
#define GWST 40     // W smem stride (halves)
#define A_EL (GBM * GAST)     // 2560 halves
#define W_EL (128 * GWST)     // 5120 halves

__global__ __launch_bounds__(256, 2)
void gemm_wmma_kernel(const __nv_bfloat16* __restrict__ Ah,
                      const __nv_bfloat16* __restrict__ Al,
                      const __nv_bfloat16* __restrict__ Wh,
                      const __nv_bfloat16* __restrict__ Wl,
                      float* __restrict__ out,
                      int Brows)
{
    __shared__ __align__(16) __nv_bfloat16 Ahs[A_EL];
    __shared__ __align__(16) __nv_bfloat16 Als[A_EL];
    __shared__ __align__(16) __nv_bfloat16 Whs[W_EL];
    __shared__ __align__(16) __nv_bfloat16 Wls[W_EL];

    int tid = threadIdx.x;
    int w = tid >> 5;
    int wm = w & 1, wn = w >> 1;       // 2 x 4 warp grid
    int row0 = blockIdx.x * GBM;
    int m0 = wm * 32, n0 = wn * 32;

    // stage indices
    int ar = tid >> 2, ac8 = (tid & 3) * 8;          // A: 64 rows x 32 cols
    int wr0 = tid >> 2, wr1 = 64 + (tid >> 2);       // W: 128 rows x 32 cols
    int wc8 = (tid & 3) * 8;

    wmma::fragment<wmma::accumulator, 16, 16, 16, float> acc[2][2];
#pragma unroll
    for (int i = 0; i < 2; i++)
#pragma unroll
        for (int j = 0; j < 2; j++)
            wmma::fill_fragment(acc[i][j], 0.0f);

    // prefetch chunk 0
    uint4 pa_h, pa_l, pw_h0, pw_h1, pw_l0, pw_l1;
    {
        pa_h = make_uint4(0, 0, 0, 0);
        pa_l = make_uint4(0, 0, 0, 0);
        if (row0 + ar < Brows) {
            pa_h = *(const uint4*)&Ah[(size_t)(row0 + ar) * 256 + ac8];
            pa_l = *(const uint4*)&Al[(size_t)(row0 + ar) * 256 + ac8];
        }
        pw_h0 = *(const uint4*)&Wh[(size_t)wr0 * 256 + wc8];
        pw_h1 = *(const uint4*)&Wh[(size_t)wr1 * 256 + wc8];
        pw_l0 = *(const uint4*)&Wl[(size_t)wr0 * 256 + wc8];
        pw_l1 = *(const uint4*)&Wl[(size_t)wr1 * 256 + wc8];
    }
    // store chunk 0
    *(uint4*)&Ahs[ar * GAST + ac8]  = pa_h;
    *(uint4*)&Als[ar * GAST + ac8]  = pa_l;
    *(uint4*)&Whs[wr0 * GWST + wc8] = pw_h0;
    *(uint4*)&Whs[wr1 * GWST + wc8] = pw_h1;
    *(uint4*)&Wls[wr0 * GWST + wc8] = pw_l0;
    *(uint4*)&Wls[wr1 * GWST + wc8] = pw_l1;
    __syncthreads();

#pragma unroll
    for (int chunk = 0; chunk < 8; chunk++) {
        // prefetch next chunk into registers (overlaps with mma below)
        if (chunk < 7) {
            int kc = (chunk + 1) * 32;
            pa_h = make_uint4(0, 0, 0, 0);
            pa_l = make_uint4(0, 0, 0, 0);
            if (row0 + ar < Brows) {
                pa_h = *(const uint4*)&Ah[(size_t)(row0 + ar) * 256 + kc + ac8];
                pa_l = *(const uint4*)&Al[(size_t)(row0 + ar) * 256 + kc + ac8];
            }
            pw_h0 = *(const uint4*)&Wh[(size_t)wr0 * 256 + kc + wc8];
            pw_h1 = *(const uint4*)&Wh[(size_t)wr1 * 256 + kc + wc8];
            pw_l0 = *(const uint4*)&Wl[(size_t)wr0 * 256 + kc + wc8];
            pw_l1 = *(const uint4*)&Wl[(size_t)wr1 * 256 + kc + wc8];
        }

        // compute current chunk
#pragma unroll
        for (int kk = 0; kk < 32; kk += 16) {
            wmma::fragment<wmma::matrix_a, 16, 16, 16, __nv_bfloat16, wmma::row_major> fah[2], fal[2];
            wmma::fragment<wmma::matrix_b, 16, 16, 16, __nv_bfloat16, wmma::col_major> fbh[2], fbl[2];
#pragma unroll
            for (int i = 0; i < 2; i++) {
                wmma::load_matrix_sync(fah[i], &Ahs[(m0 + i * 16) * GAST + kk], GAST);
                wmma::load_matrix_sync(fal[i], &Als[(m0 + i * 16) * GAST + kk], GAST);
            }
#pragma unroll
            for (int j = 0; j < 2; j++) {
                wmma::load_matrix_sync(fbh[j], &Whs[(n0 + j * 16) * GWST + kk], GWST);
                wmma::load_matrix_sync(fbl[j], &Wls[(n0 + j * 16) * GWST + kk], GWST);
            }
#pragma unroll
            for (int i = 0; i < 2; i++)
#pragma unroll
                for (int j = 0; j < 2; j++) {
                    wmma::mma_sync(acc[i][j], fah[i], fbh[j], acc[i][j]);
                    wmma::mma_sync(acc[i][j], fal[i], fbh[j], acc[i][j]);
                    wmma::mma_sync(acc[i][j], fah[i], fbl[j], acc[i][j]);
                }
        }

        if (chunk < 7) {
            __syncthreads();   // all warps done reading current chunk
            *(uint4*)&Ahs[ar * GAST + ac8]  = pa_h;
            *(uint4*)&Als[ar * GAST + ac8]  = pa_l;
            *(uint4*)&Whs[wr0 * GWST + wc8] = pw_h0;
            *(uint4*)&Whs[wr1 * GWST + wc8] = pw_h1;
            *(uint4*)&Wls[wr0 * GWST + wc8] = pw_l0;
            *(uint4*)&Wls[wr1 * GWST + wc8] = pw_l1;
            __syncthreads();
        }
    }

    // relu + direct store (Brows % 16 == 0 -> whole-tile guards)
#pragma unroll
    for (int i = 0; i < 2; i++) {
        int gr = row0 + m0 + i * 16;
        if (gr < Brows) {
#pragma unroll
            for (int j = 0; j < 2; j++) {
#pragma unroll
                for (int e = 0; e < acc[i][j].num_elements; e++)
                    acc[i][j].x[e] = fmaxf(acc[i][j].x[e], 0.0f);
                wmma::store_matrix_sync(&out[(size_t)gr * FDIM + n0 + j * 16],
                                        acc[i][j], FDIM, wmma::mem_row_major);
            }
        }
    }
}

// ---------------------------------------------------------------------------
extern "C" void kernel_launch(void* const* d_in, const int* in_sizes, int n_in,
                              void* d_out, int out_size)
{
    const int*   nodes      = (const int*)d_in[0];
    const int*   neigh_idx  = (const int*)d_in[1];
    const float* self_table = (const float*)d_in[2];
    const float* neigh_tab  = (const float*)d_in[3];
    const float* center     = (const float*)d_in[4];
    const float* cmask      = (const float*)d_in[5];
    const float* weight     = (const float*)d_in[6];
    const float* alpha      = (const float*)d_in[7];
    float*       out        = (float*)d_out;

    int B = in_sizes[0];
    int N = in_sizes[3] / FDIM;

    float *pd, *c2;
    __half* prod;
    __nv_bfloat16 *ch, *cl, *wh, *wl;
    cudaGetSymbolAddress((void**)&prod, g_prod);
    cudaGetSymbolAddress((void**)&pd,   g_pdot);
    cudaGetSymbolAddress((void**)&c2,   g_c2);
    cudaGetSymbolAddress((void**)&ch,   g_comb_hi);
    cudaGetSymbolAddress((void**)&cl,   g_comb_lo);
    cudaGetSymbolAddress((void**)&wh,   g_w_hi);
    cudaGetSymbolAddress((void**)&wl,   g_w_lo);

    prep_kernel<<<65, 512>>>(weight, wh, wl, center, c2);
    precompute_kernel<<<(N + 31) / 32, 128>>>(neigh_tab, center, alpha, cmask,
                                              c2, prod, pd, N);
    row_kernel<<<(B + 7) / 8, 256>>>(nodes, neigh_idx, self_table, alpha,
                                     pd, prod, ch, cl, B);
    gemm_wmma_kernel<<<(B + GBM - 1) / GBM, 256>>>(ch, cl, wh, wl, out, B);
}

// round 12
// speedup vs baseline: 1.5153x; 1.1245x over previous
#include <cuda_runtime.h>
#include <cuda_bf16.h>
#include <cuda_fp16.h>
#include <mma.h>
#include <cstdint>

using namespace nvcuda;

#define FDIM 128
#define SNEI 10
#define KCLU 16
#define NMAX 200704
#define BMAX 20480

typedef unsigned long long ull;

// scratch (__device__ globals per allocation rules)
__device__ float  g_pdot[NMAX];
__device__ float  g_c2[16];
__device__ __half g_prod[(size_t)NMAX * FDIM];
__device__ __half g_comb_h[(size_t)BMAX * 256];   // fp16 hi of combined
__device__ __half g_comb_l[(size_t)BMAX * 256];   // fp16 lo residual
__device__ __half g_w_h[128 * 256];               // fp16 weight

#define FFMA2(d, a, b, c) \
    asm("fma.rn.f32x2 %0, %1, %2, %3;" : "=l"(d) : "l"(a), "l"(b), "l"(c))
#define PACK2(d, lo, hi) \
    asm("mov.b64 %0, {%1, %2};" : "=l"(d) : "f"(lo), "f"(hi))
#define UNPACK2(lo, hi, v) \
    asm("mov.b64 {%0, %1}, %2;" : "=f"(lo), "=f"(hi) : "l"(v))

// ---------------------------------------------------------------------------
// prep: blocks 0..63 convert W to fp16 (512 thr); block 64 computes c2.
// ---------------------------------------------------------------------------
__global__ __launch_bounds__(512)
void prep_kernel(const float* __restrict__ w,
                 __half* __restrict__ wh,
                 const float* __restrict__ center,
                 float* __restrict__ c2)
{
    if (blockIdx.x < 64) {
        int i = blockIdx.x * 512 + threadIdx.x;
        wh[i] = __float2half(w[i]);
    } else {
        int wp = threadIdx.x >> 5, l = threadIdx.x & 31;  // 16 warps
        float4 v = ((const float4*)center)[wp * 32 + l];
        float s = v.x * v.x + v.y * v.y + v.z * v.z + v.w * v.w;
#pragma unroll
        for (int o = 16; o; o >>= 1) s += __shfl_xor_sync(0xffffffffu, s, o);
        if (l == 0) c2[wp] = s;
    }
}

// ---------------------------------------------------------------------------
// Precompute per node n (32 nodes / block, 128 threads, quarter-row split)
// (round-10/11 proven version)
// ---------------------------------------------------------------------------
#define RS4  132
#define QST  20

__global__ __launch_bounds__(128)
void precompute_kernel(const float* __restrict__ neigh_table,
                       const float* __restrict__ center,
                       const float* __restrict__ alpha,
                       const float* __restrict__ cmask,
                       const float* __restrict__ c2g,
                       __half* __restrict__ prod,
                       float* __restrict__ pdot,
                       int N)
{
    __shared__ __align__(16) float rows_s[32 * RS4];
    __shared__ __align__(16) float cen_s[16 * 128];
    __shared__ __align__(16) float alp_s[128];
    __shared__ __align__(16) float q_s[32 * QST];
    __shared__ float c2_s[16];

    int t = threadIdx.x;
    int base = blockIdx.x * 32;
    int n = t & 31, h = t >> 5;

    ull mp[8];
#pragma unroll
    for (int kp = 0; kp < 8; kp++) {
        float m0 = cmask[(2 * kp) * FDIM + t];
        float m1 = cmask[(2 * kp + 1) * FDIM + t];
        PACK2(mp[kp], m0, m1);
    }

#pragma unroll
    for (int j = 0; j < 8; j++) {
        int i = j * 128 + t;
        int r = i >> 5, c = i & 31;
        float4 v = make_float4(0.f, 0.f, 0.f, 0.f);
        if (base + r < N)
            v = ((const float4*)neigh_table)[(size_t)(base + r) * 32 + c];
        *(float4*)&rows_s[r * RS4 + c * 4] = v;
    }
#pragma unroll
    for (int j = 0; j < 4; j++)
        ((float4*)cen_s)[j * 128 + t] = ((const float4*)center)[j * 128 + t];
    if (t < 32) ((float4*)alp_s)[t] = ((const float4*)alpha)[32 + t];
    if (t < 16) c2_s[t] = c2g[t];
    __syncthreads();

    ull crp[16], n2p = 0ull, adp = 0ull;
#pragma unroll
    for (int k = 0; k < 16; k++) crp[k] = 0ull;

    {
        const float4* row = (const float4*)&rows_s[n * RS4 + h * 32];
#pragma unroll
        for (int q = 0; q < 8; q++) {
            float4 x = row[q];
            ull xp0, xp1;
            PACK2(xp0, x.x, x.y);
            PACK2(xp1, x.z, x.w);
            ulonglong2 ap = ((const ulonglong2*)(alp_s + h * 32))[q];
            FFMA2(adp, xp0, ap.x, adp);
            FFMA2(adp, xp1, ap.y, adp);
            FFMA2(n2p, xp0, xp0, n2p);
            FFMA2(n2p, xp1, xp1, n2p);
#pragma unroll
            for (int k = 0; k < 16; k++) {
                ulonglong2 cp = ((const ulonglong2*)(cen_s + k * 128 + h * 32))[q];
                FFMA2(crp[k], xp0, cp.x, crp[k]);
                FFMA2(crp[k], xp1, cp.y, crp[k]);
            }
        }
    }

    float cr[16], n2v, adv;
    {
        float lo, hi;
#pragma unroll
        for (int k = 0; k < 16; k++) { UNPACK2(lo, hi, crp[k]); cr[k] = lo + hi; }
        UNPACK2(lo, hi, n2p); n2v = lo + hi;
        UNPACK2(lo, hi, adp); adv = lo + hi;
    }
    __syncthreads();
    float* part_s = cen_s;
    if (h >= 1) {
        float* p = &part_s[(h - 1) * 640 + n * 20];
#pragma unroll
        for (int k = 0; k < 16; k++) p[k] = cr[k];
        p[16] = n2v;
        p[17] = adv;
    }
    __syncthreads();
    if (h == 0) {
        float n2t = n2v, adt = adv;
#pragma unroll
        for (int p = 0; p < 3; p++) {
            n2t += part_s[p * 640 + n * 20 + 16];
            adt += part_s[p * 640 + n * 20 + 17];
        }
        float bse = n2t + 1.0f;
#pragma unroll
        for (int k = 0; k < 16; k++) {
            float crt = cr[k] + part_s[n * 20 + k] + part_s[640 + n * 20 + k]
                      + part_s[1280 + n * 20 + k];
            float den = fmaf(-2.0f, crt, bse + c2_s[k]);
            q_s[n * QST + k] = 1.0f / den;
        }
        if (base + n < N) pdot[base + n] = adt;
    }
    __syncthreads();

    int nlim = min(32, N - base);
    for (int nn = 0; nn < nlim; nn++) {
        const ulonglong2* qp2 = (const ulonglong2*)&q_s[nn * QST];
        ull acc = 0ull;
#pragma unroll
        for (int kp = 0; kp < 4; kp++) {
            ulonglong2 qq = qp2[kp];
            FFMA2(acc, qq.x, mp[2 * kp],     acc);
            FFMA2(acc, qq.y, mp[2 * kp + 1], acc);
        }
        float lo, hi; UNPACK2(lo, hi, acc);
        float x = rows_s[nn * RS4 + t];
        prod[(size_t)(base + nn) * FDIM + t] = __float2half(x * (lo + hi));
    }
}

// ---------------------------------------------------------------------------
// Row kernel: warp per row; gathers fp16 prod rows; emits fp16 hi/lo comb.
// ---------------------------------------------------------------------------
__global__ __launch_bounds__(256)
void row_kernel(const int* __restrict__ nodes,
                const int* __restrict__ neigh_idx,
                const float* __restrict__ self_table,
                const float* __restrict__ alpha,
                const float* __restrict__ pdot,
                const __half* __restrict__ prod,
                __half* __restrict__ comb_hi,
                __half* __restrict__ comb_lo,
                int B)
{
    int wid = threadIdx.x >> 5, lane = threadIdx.x & 31;
    int b = blockIdx.x * 8 + wid;
    if (b >= B) return;

    int node = nodes[b];
    int idx[SNEI];
#pragma unroll
    for (int s = 0; s < SNEI; s++) idx[s] = neigh_idx[b * SNEI + s];

    float4 sf = ((const float4*)self_table)[(size_t)node * 32 + lane];
    uint2 praw[SNEI];
#pragma unroll
    for (int s = 0; s < SNEI; s++)
        praw[s] = ((const uint2*)(prod + (size_t)idx[s] * FDIM))[lane];
    float pd[SNEI];
#pragma unroll
    for (int s = 0; s < SNEI; s++) pd[s] = pdot[idx[s]];

    float4 al = ((const float4*)alpha)[lane];
    float d = sf.x * al.x + sf.y * al.y + sf.z * al.z + sf.w * al.w;
#pragma unroll
    for (int o = 16; o; o >>= 1) d += __shfl_xor_sync(0xffffffffu, d, o);

    float e[SNEI], sum = 0.f;
#pragma unroll
    for (int s = 0; s < SNEI; s++) {
        float l = fmaxf(d + pd[s], 0.f);
        e[s] = __expf(l);
        sum += e[s];
    }
    float inv = 1.0f / sum;

    float4 agg = make_float4(0.f, 0.f, 0.f, 0.f);
#pragma unroll
    for (int s = 0; s < SNEI; s++) {
        float w = e[s] * inv;
        float2 f01 = __half22float2(*(const __half2*)&praw[s].x);
        float2 f23 = __half22float2(*(const __half2*)&praw[s].y);
        agg.x = fmaf(w, f01.x, agg.x);
        agg.y = fmaf(w, f01.y, agg.y);
        agg.z = fmaf(w, f23.x, agg.z);
        agg.w = fmaf(w, f23.y, agg.w);
    }

    float v[8] = {sf.x, sf.y, sf.z, sf.w, agg.x, agg.y, agg.z, agg.w};
    __half hh[8], ll[8];
#pragma unroll
    for (int i = 0; i < 8; i++) {
        hh[i] = __float2half(v[i]);
        ll[i] = __float2half(v[i] - __half2float(hh[i]));
    }
    __half2* ch = (__half2*)(comb_hi + (size_t)b * 256);
    __half2* cl = (__half2*)(comb_lo + (size_t)b * 256);
    ch[lane * 2]          = __halves2half2(hh[0], hh[1]);
    ch[lane * 2 + 1]      = __halves2half2(hh[2], hh[3]);
    ch[64 + lane * 2]     = __halves2half2(hh[4], hh[5]);
    ch[64 + lane * 2 + 1] = __halves2half2(hh[6], hh[7]);
    cl[lane * 2]          = __halves2half2(ll[0], ll[1]);
    cl[lane * 2 + 1]      = __halves2half2(ll[2], ll[3]);
    cl[64 + lane * 2]     = __halves2half2(ll[4], ll[5]);
    cl[64 + lane * 2 + 1] = __halves2half2(ll[6], ll[7]);
}

// ---------------------------------------------------------------------------
// fp16 wmma GEMM, 2 products: out = relu((Ah + Al) @ W16^T)
// BM=64, BN=128, BK=64, 256 threads (2x4 warps, 32x32 tiles),
// double-buffered smem (72 KB), 2 blocks/SM, register prefetch.
// ---------------------------------------------------------------------------
#define GBM  64
#define GBK  64
#define AST  72                    // smem stride (halves)
#define WST  72
#define A_CH (GBM * AST)           // 4608 halves per A matrix per buffer
#define W_CH (128 * WST)           // 9216 halves per buffer
#define OFF_AH 0
#define OFF_AL (2 * A_CH)          // [2 buf][A_CH]
#define OFF_W  (4 * A_CH)
#define GSMH   (OFF_W + 2 * W_CH)  // total halves = 36864 -> 73728 B

__global__ __launch_bounds__(256, 2)
void gemm_wmma_kernel(const __half* __restrict__ Ah,
                      const __half* __restrict__ Al,
                      const __half* __restrict__ W16,
                      float* __restrict__ out,
                      int Brows)
{
    extern __shared__ __align__(16) __half smg[];
    __half* Ahs = smg + OFF_AH;    // [2][A_CH]
    __half* Als = smg + OFF_AL;    // [2][A_CH]
    __half* Ws  = smg + OFF_W;     // [2][W_CH]

    int tid = threadIdx.x;
    int w = tid >> 5;
    int wm = w & 1, wn = w >> 1;   // 2 x 4 warp grid, 32x32 tiles
    int row0 = blockIdx.x * GBM;
    int m0 = wm * 32, n0 = wn * 32;

    // stage indices: A 64x64 halves = 512 uint4 (2/thr); W 128x64 = 1024 (4/thr)
    int ar = tid >> 3;                  // wrong for j split; computed per j below
    (void)ar;

    wmma::fragment<wmma::accumulator, 16, 16, 16, float> acc[2][2];
#pragma unroll
    for (int i = 0; i < 2; i++)
#pragma unroll
        for (int j = 0; j < 2; j++)
            wmma::fill_fragment(acc[i][j], 0.0f);

    uint4 pah[2], pal[2], pw[4];

    // prefetch + store chunk 0
#pragma unroll
    for (int j = 0; j < 2; j++) {
        int i = j * 256 + tid;
        int r = i >> 3, c8 = (i & 7) * 8;
        pah[j] = make_uint4(0, 0, 0, 0);
        pal[j] = make_uint4(0, 0, 0, 0);
        if (row0 + r < Brows) {
            pah[j] = *(const uint4*)&Ah[(size_t)(row0 + r) * 256 + c8];
            pal[j] = *(const uint4*)&Al[(size_t)(row0 + r) * 256 + c8];
        }
    }
#pragma unroll
    for (int j = 0; j < 4; j++) {
        int i = j * 256 + tid;
        int r = i >> 3, c8 = (i & 7) * 8;
        pw[j] = *(const uint4*)&W16[(size_t)r * 256 + c8];
    }
#pragma unroll
    for (int j = 0; j < 2; j++) {
        int i = j * 256 + tid;
        int r = i >> 3, c8 = (i & 7) * 8;
        *(uint4*)&Ahs[r * AST + c8] = pah[j];
        *(uint4*)&Als[r * AST + c8] = pal[j];
    }
#pragma unroll
    for (int j = 0; j < 4; j++) {
        int i = j * 256 + tid;
        int r = i >> 3, c8 = (i & 7) * 8;
        *(uint4*)&Ws[r * WST + c8] = pw[j];
    }
    __syncthreads();

    int buf = 0;
#pragma unroll
    for (int chunk = 0; chunk < 4; chunk++) {
        // prefetch next chunk into registers
        if (chunk < 3) {
            int kc = (chunk + 1) * GBK;
#pragma unroll
            for (int j = 0; j < 2; j++) {
                int i = j * 256 + tid;
                int r = i >> 3, c8 = (i & 7) * 8;
                pah[j] = make_uint4(0, 0, 0, 0);
                pal[j] = make_uint4(0, 0, 0, 0);
                if (row0 + r < Brows) {
                    pah[j] = *(const uint4*)&Ah[(size_t)(row0 + r) * 256 + kc + c8];
                    pal[j] = *(const uint4*)&Al[(size_t)(row0 + r) * 256 + kc + c8];
                }
            }
#pragma unroll
            for (int j = 0; j < 4; j++) {
                int i = j * 256 + tid;
                int r = i >> 3, c8 = (i & 7) * 8;
                pw[j] = *(const uint4*)&W16[(size_t)r * 256 + kc + c8];
            }
        }

        // compute current chunk: 4 k-steps of 16
        const __half* Ab_h = Ahs + buf * A_CH;
        const __half* Ab_l = Als + buf * A_CH;
        const __half* Wb   = Ws  + buf * W_CH;
#pragma unroll
        for (int kk = 0; kk < GBK; kk += 16) {
            wmma::fragment<wmma::matrix_a, 16, 16, 16, __half, wmma::row_major> fah[2], fal[2];
            wmma::fragment<wmma::matrix_b, 16, 16, 16, __half, wmma::col_major> fb[2];
#pragma unroll
            for (int i = 0; i < 2; i++) {
                wmma::load_matrix_sync(fah[i], &Ab_h[(m0 + i * 16) * AST + kk], AST);
                wmma::load_matrix_sync(fal[i], &Ab_l[(m0 + i * 16) * AST + kk], AST);
            }
#pragma unroll
            for (int j = 0; j < 2; j++)
                wmma::load_matrix_sync(fb[j], &Wb[(n0 + j * 16) * WST + kk], WST);
#pragma unroll
            for (int i = 0; i < 2; i++)
#pragma unroll
                for (int j = 0; j < 2; j++) {
                    wmma::mma_sync(acc[i][j], fah[i], fb[j], acc[i][j]);
                    wmma::mma_sync(acc[i][j], fal[i], fb[j], acc[i][j]);
                }
        }

        // store prefetched chunk into other buffer
        if (chunk < 3) {
            int nb = buf ^ 1;
            __syncthreads();
#pragma unroll
            for (int j = 0; j < 2; j++) {
                int i = j * 256 + tid;
                int r = i >> 3, c8 = (i & 7) * 8;
                *(uint4*)&Ahs[nb * A_CH + r * AST + c8] = pah[j];
                *(uint4*)&Als[nb * A_CH + r * AST + c8] = pal[j];
            }
#pragma unroll
            for (int j = 0; j < 4; j++) {
                int i = j * 256 + tid;
                int r = i >> 3, c8 = (i & 7) * 8;
                *(uint4*)&Ws[nb * W_CH + r * WST + c8] = pw[j];
            }
            __syncthreads();
            buf = nb;
        }
    }

    // relu + direct store
#pragma unroll
    for (int i = 0; i < 2; i++) {
        int gr = row0 + m0 + i * 16;
        if (gr < Brows) {
#pragma unroll
            for (int j = 0; j < 2; j++) {
#pragma unroll
                for (int e = 0; e < acc[i][j].num_elements; e++)
                    acc[i][j].x[e] = fmaxf(acc[i][j].x[e], 0.0f);
                wmma::store_matrix_sync(&out[(size_t)gr * FDIM + n0 + j * 16],
                                        acc[i][j], FDIM, wmma::mem_row_major);
            }
        }
    }
}

// ---------------------------------------------------------------------------
extern "C" void kernel_launch(void* const* d_in, const int* in_sizes, int n_in,
                              void* d_out, int out_size)
{
    const int*   nodes      = (const int*)d_in[0];
    const int*   neigh_idx  = (const int*)d_in[1];
    const float* self_table = (const float*)d_in[2];
    const float* neigh_tab  = (const float*)d_in[3];
    const float* center     = (const float*)d_in[4];
    const float* cmask      = (const float*)d_in[5];
    const float* weight     = (const float*)d_in[6];
    const float* alpha      = (const float*)d_in[7];
    float*       out        = (float*)d_out;

    int B = in_sizes[0];
    int N = in_sizes[3] / FDIM;

    float *pd, *c2;
    __half *prod, *ch, *cl, *wh;
    cudaGetSymbolAddress((void**)&prod, g_prod);
    cudaGetSymbolAddress((void**)&pd,   g_pdot);
    cudaGetSymbolAddress((void**)&c2,   g_c2);
    cudaGetSymbolAddress((void**)&ch,   g_comb_h);
    cudaGetSymbolAddress((void**)&cl,   g_comb_l);
    cudaGetSymbolAddress((void**)&wh,   g_w_h);

    cudaFuncSetAttribute(gemm_wmma_kernel,
                         cudaFuncAttributeMaxDynamicSharedMemorySize,
                         GSMH * (int)sizeof(__half));

    prep_kernel<<<65, 512>>>(weight, wh, center, c2);
    precompute_kernel<<<(N + 31) / 32, 128>>>(neigh_tab, center, alpha, cmask,
                                              c2, prod, pd, N);
    row_kernel<<<(B + 7) / 8, 256>>>(nodes, neigh_idx, self_table, alpha,
                                     pd, prod, ch, cl, B);
    gemm_wmma_kernel<<<(B + GBM - 1) / GBM, 256,
                      GSMH * (int)sizeof(__half)>>>(ch, cl, wh, out, B);
}